// round 14
// baseline (speedup 1.0000x reference)
#include <cuda_runtime.h>
#include <cuda_fp16.h>
#include <math.h>
#include <stdint.h>

// ---------------------------------------------------------------------------
// MoE top-2-of-8 via pure fp16 HMMA (fp32 accumulate).
// R14: pass1 + w2-convert + pass2 fused into ONE launch. Pass1 tiles are
// mt-major and increment done[mt] (threadfence+atomic) after their epilogue;
// pass2 tiles (placed after all producers in blockIdx order -> dispatch-
// order guarantees no deadlock) spin until done[mt]==64 and w2conv==4096.
// Removes the pass1->pass2 device drain while keeping all CTAs independent
// (R12 showed in-CTA persistence loses cross-CTA overlap).
// GEMM mainloop identical to R11/R13.
// ---------------------------------------------------------------------------

#define BATCH 8192
#define NEXP  8
#define DIN   2048
#define DHID  8192
#define DOUT  2048

#define BM 128
#define BN 128
#define MAX_ROWS 17408
#define NMT (MAX_ROWS / BM)          // 136

#define A_O 0
#define B_O 16384
#define STAGE_B 32768
#define DYN_BYTES (3 * STAGE_B + 1024)

#define GATE_B 1024
#define W1CONV_B 2048
#define XCONV_B 256

#define NP1 (NMT * (DHID / BN))      // 8704 pass1 tiles
#define NW2C 4096                    // w2 converter blocks
#define NGRP 512                     // 512 groups of (17 pass1 + 8 conv) = 12800
#define MEGA_P2_BASE (NGRP * 25)
#define NP2 (NMT * (DOUT / BN))      // 2176 pass2 tiles

#define SWZ(o) ((o) ^ (((o) >> 3) & 0x70))

// ---- device scratch --------------------------------------------------------
__device__ __half g_w1h[(size_t)NEXP * DHID * DIN];
__device__ __half g_w2h[(size_t)NEXP * DOUT * DHID];
__device__ __half g_xh[(size_t)BATCH * DIN];
__device__ __half g_hh[(size_t)MAX_ROWS * DHID];
__device__ float  g_y[(size_t)MAX_ROWS * DOUT];

__device__ int   g_tok_e[BATCH * 2];
__device__ float g_tok_p[BATCH * 2];
__device__ int   g_tok_slot[BATCH * 2];
__device__ int   g_pair_token[MAX_ROWS];
__device__ int   g_offsets[NEXP + 1];
__device__ int   g_mt_done[NMT];
__device__ int   g_w2c_done;

// ---- helpers ----------------------------------------------------------------
__device__ __forceinline__ uint32_t smem_u32(const void* p) {
    uint32_t a;
    asm("{ .reg .u64 t; cvta.to.shared.u64 t, %1; cvt.u32.u64 %0, t; }"
        : "=r"(a) : "l"(p));
    return a;
}
__device__ __forceinline__ void cp16(uint32_t s, const void* g) {
    asm volatile("cp.async.cg.shared.global [%0], [%1], 16;" :: "r"(s), "l"(g));
}
__device__ __forceinline__ void cp_commit() {
    asm volatile("cp.async.commit_group;" ::: "memory");
}
template <int N>
__device__ __forceinline__ void cp_wait() {
    asm volatile("cp.async.wait_group %0;" :: "n"(N) : "memory");
}
__device__ __forceinline__ void ldsm4(uint32_t* r, uint32_t addr) {
    asm volatile("ldmatrix.sync.aligned.m8n8.x4.shared.b16 {%0,%1,%2,%3}, [%4];"
                 : "=r"(r[0]), "=r"(r[1]), "=r"(r[2]), "=r"(r[3]) : "r"(addr));
}
__device__ __forceinline__ void mma16816(float* d, const uint32_t* a,
                                         const uint32_t* b) {
    asm volatile(
        "mma.sync.aligned.m16n8k16.row.col.f32.f16.f16.f32 "
        "{%0,%1,%2,%3}, {%4,%5,%6,%7}, {%8,%9}, {%0,%1,%2,%3};"
        : "+f"(d[0]), "+f"(d[1]), "+f"(d[2]), "+f"(d[3])
        : "r"(a[0]), "r"(a[1]), "r"(a[2]), "r"(a[3]), "r"(b[0]), "r"(b[1]));
}
__device__ __forceinline__ float geluf(float v) {
    return 0.5f * v * (1.0f + erff(v * 0.7071067811865476f));
}
__device__ __forceinline__ void conv4(const float4* __restrict__ src,
                                      uint2* __restrict__ dst, size_t i) {
    float4 v = src[i];
    __half2 h0 = __floats2half2_rn(v.x, v.y);
    __half2 h1 = __floats2half2_rn(v.z, v.w);
    dst[i] = make_uint2(*(uint32_t*)&h0, *(uint32_t*)&h1);
}

// ---------------------------------------------------------------------------
// Gating + fused w1/x fp16 conversion.
__global__ void gate_kernel(const float* __restrict__ x,
                            const float* __restrict__ gw,
                            const float4* __restrict__ w1src) {
    int b = blockIdx.x;
    if (b >= GATE_B) {
        int cb = b - GATE_B;
        if (cb < W1CONV_B) {
            size_t base = (size_t)cb * 16384;
            uint2* dst = (uint2*)g_w1h;
            for (size_t i = base + threadIdx.x; i < base + 16384; i += 256)
                conv4(w1src, dst, i);
        } else {
            size_t base = (size_t)(cb - W1CONV_B) * 16384;
            const float4* xs = (const float4*)x;
            uint2* dst = (uint2*)g_xh;
            for (size_t i = base + threadIdx.x; i < base + 16384; i += 256)
                conv4(xs, dst, i);
        }
        return;
    }
    int gtid = b * blockDim.x + threadIdx.x;
    int t = gtid >> 5;
    int lane = gtid & 31;
    if (t >= BATCH) return;
    const float* xr = x + (size_t)t * DIN;
    float acc[NEXP];
#pragma unroll
    for (int e = 0; e < NEXP; e++) acc[e] = 0.0f;
    for (int k = lane; k < DIN; k += 32) {
        float xv = __ldg(xr + k);
#pragma unroll
        for (int e = 0; e < NEXP; e++) acc[e] += xv * __ldg(gw + e * DIN + k);
    }
#pragma unroll
    for (int off = 16; off > 0; off >>= 1) {
#pragma unroll
        for (int e = 0; e < NEXP; e++)
            acc[e] += __shfl_xor_sync(0xffffffffu, acc[e], off);
    }
    if (lane == 0) {
        float v0 = -1e30f, v1 = -1e30f;
        int i0 = 0, i1 = 0;
#pragma unroll
        for (int e = 0; e < NEXP; e++) {
            float v = acc[e];
            if (v > v0) { v1 = v0; i1 = i0; v0 = v; i0 = e; }
            else if (v > v1) { v1 = v; i1 = e; }
        }
        float e1 = expf(v1 - v0);
        float s = 1.0f + e1;
        g_tok_e[2 * t + 0] = i0;
        g_tok_e[2 * t + 1] = i1;
        g_tok_p[2 * t + 0] = 1.0f / s;
        g_tok_p[2 * t + 1] = e1 / s;
    }
}

// Fused counts + offsets + ordered compaction + padding zero + counter reset.
__global__ void assign_kernel() {
    int e = blockIdx.x;
    __shared__ int cnt[NEXP];
    __shared__ int wcnt[32];
    if (threadIdx.x < NEXP) cnt[threadIdx.x] = 0;
    __syncthreads();
    for (int t = threadIdx.x; t < BATCH; t += 1024) {
        atomicAdd(&cnt[g_tok_e[2 * t + 0]], 1);
        atomicAdd(&cnt[g_tok_e[2 * t + 1]], 1);
    }
    __syncthreads();
    int base = 0;
    for (int i = 0; i < e; i++) base += ((cnt[i] + BM - 1) / BM) * BM;
    const int my_cnt = cnt[e];
    const int my_pad = ((my_cnt + BM - 1) / BM) * BM;
    if (e == 0) {
        if (threadIdx.x == 0) {
            int off = 0;
            for (int i = 0; i < NEXP; i++) {
                g_offsets[i] = off;
                off += ((cnt[i] + BM - 1) / BM) * BM;
            }
            g_offsets[NEXP] = off;
            g_w2c_done = 0;
        }
        for (int i = threadIdx.x; i < NMT; i += 1024) g_mt_done[i] = 0;
    }
    for (int i = base + my_cnt + threadIdx.x; i < base + my_pad; i += 1024)
        g_pair_token[i] = 0;

    int lane = threadIdx.x & 31;
    int wid = threadIdx.x >> 5;
    int run = base;
    for (int t0 = 0; t0 < BATCH; t0 += 1024) {
        int t = t0 + threadIdx.x;
        int sel = 0, kk = 0;
        int e0 = g_tok_e[2 * t], e1 = g_tok_e[2 * t + 1];
        if (e0 == e)      { sel = 1; kk = 0; }
        else if (e1 == e) { sel = 1; kk = 1; }
        unsigned m = __ballot_sync(0xffffffffu, sel);
        if (lane == 0) wcnt[wid] = __popc(m);
        __syncthreads();
        int prefix = 0, tot = 0;
#pragma unroll
        for (int i = 0; i < 32; i++) {
            if (i < wid) prefix += wcnt[i];
            tot += wcnt[i];
        }
        if (sel) {
            int pos = run + prefix + __popc(m & ((1u << lane) - 1u));
            g_pair_token[pos] = t;
            g_tok_slot[2 * t + kk] = pos;
        }
        run += tot;
        __syncthreads();
    }
}

// out[t] = p0 * y[slot0] + p1 * y[slot1]
__global__ void combine_kernel(float* __restrict__ out) {
    int t = blockIdx.x;
    int s0 = g_tok_slot[2 * t], s1 = g_tok_slot[2 * t + 1];
    float p0 = g_tok_p[2 * t], p1 = g_tok_p[2 * t + 1];
    const float4* y0 = (const float4*)(g_y + (size_t)s0 * DOUT);
    const float4* y1 = (const float4*)(g_y + (size_t)s1 * DOUT);
    float4* o = (float4*)(out + (size_t)t * DOUT);
#pragma unroll
    for (int i = threadIdx.x; i < DOUT / 4; i += 256) {
        float4 a = y0[i], b = y1[i];
        o[i] = make_float4(p0 * a.x + p1 * b.x, p0 * a.y + p1 * b.y,
                           p0 * a.z + p1 * b.z, p0 * a.w + p1 * b.w);
    }
}

// ---------------------------------------------------------------------------
// GEMM tile (identical mainloop to R11/R13). Returns false if tile is padding.
// P2 tiles spin on dependency counters before touching g_hh / g_w2h.
// ---------------------------------------------------------------------------
template <int KDIM, bool P1>
__device__ bool gemm_tile(int mt, int nt, const float* __restrict__ bias) {
    __shared__ int s_off[NEXP + 1];
    __shared__ int stok[BM];
    __shared__ float sbias[BN];
    extern __shared__ char dsm[];

    const int tid = threadIdx.x;
    if (tid < NEXP + 1) s_off[tid] = g_offsets[tid];
    __syncthreads();
    const int row0 = mt * BM;
    if (row0 >= s_off[NEXP]) return false;

    if (!P1) {
        if (tid == 0) {
            while (*(volatile int*)&g_w2c_done < NW2C ||
                   *(volatile int*)&g_mt_done[mt] < (DHID / BN))
                __nanosleep(200);
            __threadfence();
        }
        __syncthreads();
    }

    int e = 0;
    while (row0 >= s_off[e + 1]) e++;
    if (P1) stok[tid] = g_pair_token[row0 + tid];
    sbias[tid] = bias[(size_t)e * (P1 ? DHID : DOUT) + (size_t)nt * BN + tid];
    __syncthreads();

    const __half* Ag = P1 ? g_xh : g_hh;
    const __half* Bg = P1 ? g_w1h : g_w2h;

    uintptr_t pal = ((uintptr_t)dsm + 1023) & ~(uintptr_t)1023;
    const uint32_t su = smem_u32((void*)pal);

    // ---- producer mapping ----
    const int ch = tid & 7;
    const int rb = tid >> 3;
    uint32_t aOff[8];
    const size_t brow0 = (size_t)e * (P1 ? DHID : DOUT) + (size_t)nt * BN;
    const __half* bP0 = Bg + (brow0 + rb) * (size_t)KDIM + ch * 8;
#pragma unroll
    for (int i = 0; i < 8; i++) {
        int r = rb + i * 16;
        size_t ga = P1 ? (size_t)stok[r] * KDIM : (size_t)(row0 + r) * KDIM;
        aOff[i] = (uint32_t)((ga + ch * 8) * 2);
    }
    const uint32_t swz0 = SWZ((uint32_t)rb * 128 + (uint32_t)ch * 16);
    const char* Agb = (const char*)Ag;

    auto issue = [&](int kt, int st) {
        uint32_t sb = su + st * STAGE_B;
        uint32_t ko = (uint32_t)kt * 128;
#pragma unroll
        for (int i = 0; i < 8; i++)
            cp16(sb + A_O + swz0 + i * 2048, Agb + aOff[i] + ko);
#pragma unroll
        for (int i = 0; i < 8; i++)
            cp16(sb + B_O + swz0 + i * 2048,
                 bP0 + (size_t)i * 16 * KDIM + kt * 64);
    };

    issue(0, 0);
    cp_commit();
    issue(1, 1);
    cp_commit();

    // ---- consumer mapping ----
    const int wid = tid >> 5, lane = tid & 31;
    const int warp_m = (wid >> 1) * 64;
    const int warp_n = (wid & 1) * 64;
    const uint32_t xorv = (uint32_t)(lane & 7) << 4;
    const uint32_t kxA = (uint32_t)((lane >> 4) << 4);
    const uint32_t rowA =
        (uint32_t)(warp_m + (lane & 7) + ((lane >> 3) & 1) * 8) * 128;
    const uint32_t kxB = (uint32_t)(((lane >> 3) & 1) << 4);
    const uint32_t rowB =
        (uint32_t)(warp_n + (lane & 7) + ((lane >> 4) & 1) * 8) * 128;

    float acc[4][8][4];
#pragma unroll
    for (int i = 0; i < 4; i++)
#pragma unroll
        for (int j = 0; j < 8; j++)
#pragma unroll
            for (int q = 0; q < 4; q++) acc[i][j][q] = 0.0f;

    uint32_t ah[2][4][4], bh[2][4][4];

    auto load_frags = [&](uint32_t sb, int s, int buf) {
        const uint32_t ktA = (((uint32_t)(s * 32)) + kxA) ^ xorv;
        const uint32_t ktB = (((uint32_t)(s * 32)) + kxB) ^ xorv;
#pragma unroll
        for (int mi = 0; mi < 4; mi++)
            ldsm4(ah[buf][mi], sb + A_O + rowA + mi * 2048 + ktA);
#pragma unroll
        for (int j = 0; j < 4; j++)
            ldsm4(bh[buf][j], sb + B_O + rowB + j * 2048 + ktB);
    };

    const int NCH = KDIM / 64;
#pragma unroll 1
    for (int c = 0; c < NCH; c++) {
        cp_wait<1>();
        __syncthreads();
        if (c + 2 < NCH) issue(c + 2, (c + 2) % 3);
        cp_commit();
        const uint32_t sb = su + (c % 3) * STAGE_B;
        load_frags(sb, 0, 0);
#pragma unroll
        for (int s = 0; s < 4; s++) {
            const int cur = s & 1;
            if (s < 3) load_frags(sb, s + 1, cur ^ 1);
#pragma unroll
            for (int mi = 0; mi < 4; mi++)
#pragma unroll
                for (int nj = 0; nj < 8; nj++)
                    mma16816(acc[mi][nj], ah[cur][mi],
                             &bh[cur][nj >> 1][(nj & 1) * 2]);
        }
    }

    // ---- epilogue ----
    const int g = lane >> 2, t4 = lane & 3;
    if (P1) {
#pragma unroll
        for (int mi = 0; mi < 4; mi++) {
            int r0 = warp_m + mi * 16 + g;
#pragma unroll
            for (int nj = 0; nj < 8; nj++) {
                int cB = warp_n + nj * 8 + 2 * t4;
                float b0v = sbias[cB], b1v = sbias[cB + 1];
                float v00 = geluf(acc[mi][nj][0] + b0v);
                float v01 = geluf(acc[mi][nj][1] + b1v);
                float v10 = geluf(acc[mi][nj][2] + b0v);
                float v11 = geluf(acc[mi][nj][3] + b1v);
                size_t gc = (size_t)nt * BN + cB;
                __half2 p0 = __floats2half2_rn(v00, v01);
                __half2 p1 = __floats2half2_rn(v10, v11);
                *(uint32_t*)(g_hh + (size_t)(row0 + r0) * DHID + gc) =
                    *(uint32_t*)&p0;
                *(uint32_t*)(g_hh + (size_t)(row0 + r0 + 8) * DHID + gc) =
                    *(uint32_t*)&p1;
            }
        }
    } else {
#pragma unroll
        for (int mi = 0; mi < 4; mi++) {
            int r0 = warp_m + mi * 16 + g;
            float* y0 = g_y + (size_t)(row0 + r0) * DOUT + (size_t)nt * BN;
            float* y1 = g_y + (size_t)(row0 + r0 + 8) * DOUT + (size_t)nt * BN;
#pragma unroll
            for (int nj = 0; nj < 8; nj++) {
                int cB = warp_n + nj * 8 + 2 * t4;
                float b0v = sbias[cB], b1v = sbias[cB + 1];
                *(float2*)(y0 + cB) =
                    make_float2(acc[mi][nj][0] + b0v, acc[mi][nj][1] + b1v);
                *(float2*)(y1 + cB) =
                    make_float2(acc[mi][nj][2] + b0v, acc[mi][nj][3] + b1v);
            }
        }
    }
    return true;
}

// ---------------------------------------------------------------------------
// Mega kernel: [0,12800) = interleaved pass1 tiles (mt-major) + w2 convert;
// [12800, 12800+NP2) = pass2 tiles (mt-major), gated on counters.
// ---------------------------------------------------------------------------
__global__ void __launch_bounds__(128, 2)
mega_kernel(const float* __restrict__ b1, const float* __restrict__ b2,
            const float4* __restrict__ w2src) {
    const int b = blockIdx.x;
    if (b < MEGA_P2_BASE) {
        const int grp = b / 25, rem = b % 25;
        if (rem < 17) {
            const int p = grp * 17 + rem;                 // 0..8703
            const int mt = p >> 6, nt = p & 63;
            bool did = gemm_tile<DIN, true>(mt, nt, b1);
            if (did) {
                __threadfence();
                __syncthreads();
                if (threadIdx.x == 0) atomicAdd(&g_mt_done[mt], 1);
            }
        } else {
            const int ci = grp * 8 + (rem - 17);          // 0..4095
            size_t base = (size_t)ci * 8192;
            uint2* dst = (uint2*)g_w2h;
            for (size_t i = base + threadIdx.x; i < base + 8192; i += 128)
                conv4(w2src, dst, i);
            __threadfence();
            __syncthreads();
            if (threadIdx.x == 0) atomicAdd(&g_w2c_done, 1);
        }
    } else {
        const int q = b - MEGA_P2_BASE;                   // 0..2175
        const int mt = q >> 4, nt = q & 15;
        gemm_tile<DHID, false>(mt, nt, b2);
    }
}

// ---------------------------------------------------------------------------
extern "C" void kernel_launch(void* const* d_in, const int* in_sizes, int n_in,
                              void* d_out, int out_size) {
    const float* x  = (const float*)d_in[0];
    const float* gw = (const float*)d_in[1];
    const float* w1 = (const float*)d_in[2];
    const float* b1 = (const float*)d_in[3];
    const float* w2 = (const float*)d_in[4];
    const float* b2 = (const float*)d_in[5];
    float* out = (float*)d_out;

    cudaFuncSetAttribute(mega_kernel,
                         cudaFuncAttributeMaxDynamicSharedMemorySize, DYN_BYTES);

    gate_kernel<<<GATE_B + W1CONV_B + XCONV_B, 256>>>(x, gw, (const float4*)w1);
    assign_kernel<<<NEXP, 1024>>>();
    mega_kernel<<<MEGA_P2_BASE + NP2, 128, DYN_BYTES>>>(b1, b2,
                                                        (const float4*)w2);
    combine_kernel<<<BATCH, 256>>>(out);
}

// round 15
// speedup vs baseline: 1.0062x; 1.0062x over previous
#include <cuda_runtime.h>
#include <cuda_fp16.h>
#include <math.h>
#include <stdint.h>

// ---------------------------------------------------------------------------
// MoE top-2-of-8 via pure fp16 HMMA (fp32 accumulate).
// R15: w1 fp32->fp16 conversion moved INTO pass1's grid with nt-granular
// counter gating (g_w1c[e*64+nt]): grid.x = [0,64) w1 converters for column
// nt=y (dispatched before that column's tiles -> no deadlock), [64,200)
// GEMM tiles, [200,264) w2 converters. Removes ~110us serial DRAM from the
// gate kernel; conversion rides under the tensor-bound GEMM (R9 pattern).
// Pass2/combine identical to R13. GEMM mainloop identical to R11/R13.
// ---------------------------------------------------------------------------

#define BATCH 8192
#define NEXP  8
#define DIN   2048
#define DHID  8192
#define DOUT  2048

#define BM 128
#define BN 128
#define MAX_ROWS 17408
#define NMT (MAX_ROWS / BM)          // 136

#define A_O 0
#define B_O 16384
#define STAGE_B 32768
#define DYN_BYTES (3 * STAGE_B + 1024)

#define GATE_B 1024
#define XCONV_B 256
#define W1C_X 64
#define W2C_X 64
#define P1_TILE_X0 W1C_X
#define P1_W2_X0 (W1C_X + NMT)

#define SWZ(o) ((o) ^ (((o) >> 3) & 0x70))

// ---- device scratch --------------------------------------------------------
__device__ __half g_w1h[(size_t)NEXP * DHID * DIN];
__device__ __half g_w2h[(size_t)NEXP * DOUT * DHID];
__device__ __half g_xh[(size_t)BATCH * DIN];
__device__ __half g_hh[(size_t)MAX_ROWS * DHID];
__device__ float  g_y[(size_t)MAX_ROWS * DOUT];

__device__ int   g_tok_e[BATCH * 2];
__device__ float g_tok_p[BATCH * 2];
__device__ int   g_tok_slot[BATCH * 2];
__device__ int   g_pair_token[MAX_ROWS];
__device__ int   g_offsets[NEXP + 1];
__device__ int   g_w1c[NEXP * 64];

// ---- helpers ----------------------------------------------------------------
__device__ __forceinline__ uint32_t smem_u32(const void* p) {
    uint32_t a;
    asm("{ .reg .u64 t; cvta.to.shared.u64 t, %1; cvt.u32.u64 %0, t; }"
        : "=r"(a) : "l"(p));
    return a;
}
__device__ __forceinline__ void cp16(uint32_t s, const void* g) {
    asm volatile("cp.async.cg.shared.global [%0], [%1], 16;" :: "r"(s), "l"(g));
}
__device__ __forceinline__ void cp_commit() {
    asm volatile("cp.async.commit_group;" ::: "memory");
}
template <int N>
__device__ __forceinline__ void cp_wait() {
    asm volatile("cp.async.wait_group %0;" :: "n"(N) : "memory");
}
__device__ __forceinline__ void ldsm4(uint32_t* r, uint32_t addr) {
    asm volatile("ldmatrix.sync.aligned.m8n8.x4.shared.b16 {%0,%1,%2,%3}, [%4];"
                 : "=r"(r[0]), "=r"(r[1]), "=r"(r[2]), "=r"(r[3]) : "r"(addr));
}
__device__ __forceinline__ void mma16816(float* d, const uint32_t* a,
                                         const uint32_t* b) {
    asm volatile(
        "mma.sync.aligned.m16n8k16.row.col.f32.f16.f16.f32 "
        "{%0,%1,%2,%3}, {%4,%5,%6,%7}, {%8,%9}, {%0,%1,%2,%3};"
        : "+f"(d[0]), "+f"(d[1]), "+f"(d[2]), "+f"(d[3])
        : "r"(a[0]), "r"(a[1]), "r"(a[2]), "r"(a[3]), "r"(b[0]), "r"(b[1]));
}
__device__ __forceinline__ float geluf(float v) {
    return 0.5f * v * (1.0f + erff(v * 0.7071067811865476f));
}
__device__ __forceinline__ void conv4(const float4* __restrict__ src,
                                      uint2* __restrict__ dst, size_t i) {
    float4 v = src[i];
    __half2 h0 = __floats2half2_rn(v.x, v.y);
    __half2 h1 = __floats2half2_rn(v.z, v.w);
    dst[i] = make_uint2(*(uint32_t*)&h0, *(uint32_t*)&h1);
}

// ---------------------------------------------------------------------------
// Gating + fused x fp16 conversion (w1 conversion moved to pass1 grid).
__global__ void gate_kernel(const float* __restrict__ x,
                            const float* __restrict__ gw) {
    int b = blockIdx.x;
    if (b >= GATE_B) {
        size_t base = (size_t)(b - GATE_B) * 16384;
        const float4* xs = (const float4*)x;
        uint2* dst = (uint2*)g_xh;
        for (size_t i = base + threadIdx.x; i < base + 16384; i += 256)
            conv4(xs, dst, i);
        return;
    }
    int gtid = b * blockDim.x + threadIdx.x;
    int t = gtid >> 5;
    int lane = gtid & 31;
    if (t >= BATCH) return;
    const float* xr = x + (size_t)t * DIN;
    float acc[NEXP];
#pragma unroll
    for (int e = 0; e < NEXP; e++) acc[e] = 0.0f;
    for (int k = lane; k < DIN; k += 32) {
        float xv = __ldg(xr + k);
#pragma unroll
        for (int e = 0; e < NEXP; e++) acc[e] += xv * __ldg(gw + e * DIN + k);
    }
#pragma unroll
    for (int off = 16; off > 0; off >>= 1) {
#pragma unroll
        for (int e = 0; e < NEXP; e++)
            acc[e] += __shfl_xor_sync(0xffffffffu, acc[e], off);
    }
    if (lane == 0) {
        float v0 = -1e30f, v1 = -1e30f;
        int i0 = 0, i1 = 0;
#pragma unroll
        for (int e = 0; e < NEXP; e++) {
            float v = acc[e];
            if (v > v0) { v1 = v0; i1 = i0; v0 = v; i0 = e; }
            else if (v > v1) { v1 = v; i1 = e; }
        }
        float e1 = expf(v1 - v0);
        float s = 1.0f + e1;
        g_tok_e[2 * t + 0] = i0;
        g_tok_e[2 * t + 1] = i1;
        g_tok_p[2 * t + 0] = 1.0f / s;
        g_tok_p[2 * t + 1] = e1 / s;
    }
}

// Fused counts + offsets + ordered compaction + padding zero + counter reset.
__global__ void assign_kernel() {
    int e = blockIdx.x;
    __shared__ int cnt[NEXP];
    __shared__ int wcnt[32];
    if (threadIdx.x < NEXP) cnt[threadIdx.x] = 0;
    __syncthreads();
    for (int t = threadIdx.x; t < BATCH; t += 1024) {
        atomicAdd(&cnt[g_tok_e[2 * t + 0]], 1);
        atomicAdd(&cnt[g_tok_e[2 * t + 1]], 1);
    }
    __syncthreads();
    int base = 0;
    for (int i = 0; i < e; i++) base += ((cnt[i] + BM - 1) / BM) * BM;
    const int my_cnt = cnt[e];
    const int my_pad = ((my_cnt + BM - 1) / BM) * BM;
    if (e == 0) {
        if (threadIdx.x == 0) {
            int off = 0;
            for (int i = 0; i < NEXP; i++) {
                g_offsets[i] = off;
                off += ((cnt[i] + BM - 1) / BM) * BM;
            }
            g_offsets[NEXP] = off;
        }
        if (threadIdx.x < NEXP * 64) g_w1c[threadIdx.x] = 0;
    }
    for (int i = base + my_cnt + threadIdx.x; i < base + my_pad; i += 1024)
        g_pair_token[i] = 0;

    int lane = threadIdx.x & 31;
    int wid = threadIdx.x >> 5;
    int run = base;
    for (int t0 = 0; t0 < BATCH; t0 += 1024) {
        int t = t0 + threadIdx.x;
        int sel = 0, kk = 0;
        int e0 = g_tok_e[2 * t], e1 = g_tok_e[2 * t + 1];
        if (e0 == e)      { sel = 1; kk = 0; }
        else if (e1 == e) { sel = 1; kk = 1; }
        unsigned m = __ballot_sync(0xffffffffu, sel);
        if (lane == 0) wcnt[wid] = __popc(m);
        __syncthreads();
        int prefix = 0, tot = 0;
#pragma unroll
        for (int i = 0; i < 32; i++) {
            if (i < wid) prefix += wcnt[i];
            tot += wcnt[i];
        }
        if (sel) {
            int pos = run + prefix + __popc(m & ((1u << lane) - 1u));
            g_pair_token[pos] = t;
            g_tok_slot[2 * t + kk] = pos;
        }
        run += tot;
        __syncthreads();
    }
}

// out[t] = p0 * y[slot0] + p1 * y[slot1]
__global__ void combine_kernel(float* __restrict__ out) {
    int t = blockIdx.x;
    int s0 = g_tok_slot[2 * t], s1 = g_tok_slot[2 * t + 1];
    float p0 = g_tok_p[2 * t], p1 = g_tok_p[2 * t + 1];
    const float4* y0 = (const float4*)(g_y + (size_t)s0 * DOUT);
    const float4* y1 = (const float4*)(g_y + (size_t)s1 * DOUT);
    float4* o = (float4*)(out + (size_t)t * DOUT);
#pragma unroll
    for (int i = threadIdx.x; i < DOUT / 4; i += 256) {
        float4 a = y0[i], b = y1[i];
        o[i] = make_float4(p0 * a.x + p1 * b.x, p0 * a.y + p1 * b.y,
                           p0 * a.z + p1 * b.z, p0 * a.w + p1 * b.w);
    }
}

// ---------------------------------------------------------------------------
// Grouped GEMM: C[128x128] = A[128xK] * B[128xK]^T, fp16 HMMA.
// Mainloop identical to R11/R13. P1 tiles gate on g_w1c[e*64+nt]==8.
// ---------------------------------------------------------------------------
template <int KDIM, bool P1>
__global__ void __launch_bounds__(128, 2)
mma_gemm(const float* __restrict__ bias, const float4* __restrict__ w1src,
         const float4* __restrict__ w2src) {
    int mt, nt;
    if (P1) {
        const int bx = blockIdx.x;
        nt = blockIdx.y;
        if (bx < W1C_X) {
            const int e = bx >> 3, sub = bx & 7;
            size_t base =
                (size_t)(e * DHID + nt * BM) * (DIN / 4) + (size_t)sub * 8192;
            uint2* dst = (uint2*)g_w1h;
            for (size_t i = base + threadIdx.x; i < base + 8192; i += 128)
                conv4(w1src, dst, i);
            __threadfence();
            __syncthreads();
            if (threadIdx.x == 0) atomicAdd(&g_w1c[e * 64 + nt], 1);
            return;
        }
        if (bx >= P1_W2_X0) {
            size_t base =
                ((size_t)(bx - P1_W2_X0) + (size_t)nt * W2C_X) * 8192;
            uint2* dst = (uint2*)g_w2h;
            for (size_t i = base + threadIdx.x; i < base + 8192; i += 128)
                conv4(w2src, dst, i);
            return;
        }
        mt = bx - P1_TILE_X0;
    } else {
        nt = blockIdx.x;
        mt = blockIdx.y;
    }

    __shared__ int s_off[NEXP + 1];
    __shared__ int stok[BM];
    __shared__ float sbias[BN];
    extern __shared__ char dsm[];

    const int tid = threadIdx.x;
    if (tid < NEXP + 1) s_off[tid] = g_offsets[tid];
    __syncthreads();
    const int row0 = mt * BM;
    if (row0 >= s_off[NEXP]) return;
    int e = 0;
    while (row0 >= s_off[e + 1]) e++;

    if (P1) {
        if (tid == 0) {
            while (*(volatile int*)&g_w1c[e * 64 + nt] < 8) __nanosleep(100);
            __threadfence();
        }
        __syncthreads();
    }

    if (P1) stok[tid] = g_pair_token[row0 + tid];
    sbias[tid] = bias[(size_t)e * (P1 ? DHID : DOUT) + (size_t)nt * BN + tid];
    __syncthreads();

    const __half* Ag = P1 ? g_xh : g_hh;
    const __half* Bg = P1 ? g_w1h : g_w2h;

    uintptr_t pal = ((uintptr_t)dsm + 1023) & ~(uintptr_t)1023;
    const uint32_t su = smem_u32((void*)pal);

    // ---- producer mapping ----
    const int ch = tid & 7;
    const int rb = tid >> 3;
    uint32_t aOff[8];
    const size_t brow0 = (size_t)e * (P1 ? DHID : DOUT) + (size_t)nt * BN;
    const __half* bP0 = Bg + (brow0 + rb) * (size_t)KDIM + ch * 8;
#pragma unroll
    for (int i = 0; i < 8; i++) {
        int r = rb + i * 16;
        size_t ga = P1 ? (size_t)stok[r] * KDIM : (size_t)(row0 + r) * KDIM;
        aOff[i] = (uint32_t)((ga + ch * 8) * 2);
    }
    const uint32_t swz0 = SWZ((uint32_t)rb * 128 + (uint32_t)ch * 16);
    const char* Agb = (const char*)Ag;

    auto issue = [&](int kt, int st) {
        uint32_t sb = su + st * STAGE_B;
        uint32_t ko = (uint32_t)kt * 128;
#pragma unroll
        for (int i = 0; i < 8; i++)
            cp16(sb + A_O + swz0 + i * 2048, Agb + aOff[i] + ko);
#pragma unroll
        for (int i = 0; i < 8; i++)
            cp16(sb + B_O + swz0 + i * 2048,
                 bP0 + (size_t)i * 16 * KDIM + kt * 64);
    };

    issue(0, 0);
    cp_commit();
    issue(1, 1);
    cp_commit();

    // ---- consumer mapping ----
    const int wid = tid >> 5, lane = tid & 31;
    const int warp_m = (wid >> 1) * 64;
    const int warp_n = (wid & 1) * 64;
    const uint32_t xorv = (uint32_t)(lane & 7) << 4;
    const uint32_t kxA = (uint32_t)((lane >> 4) << 4);
    const uint32_t rowA =
        (uint32_t)(warp_m + (lane & 7) + ((lane >> 3) & 1) * 8) * 128;
    const uint32_t kxB = (uint32_t)(((lane >> 3) & 1) << 4);
    const uint32_t rowB =
        (uint32_t)(warp_n + (lane & 7) + ((lane >> 4) & 1) * 8) * 128;

    float acc[4][8][4];
#pragma unroll
    for (int i = 0; i < 4; i++)
#pragma unroll
        for (int j = 0; j < 8; j++)
#pragma unroll
            for (int q = 0; q < 4; q++) acc[i][j][q] = 0.0f;

    uint32_t ah[2][4][4], bh[2][4][4];

    auto load_frags = [&](uint32_t sb, int s, int buf) {
        const uint32_t ktA = (((uint32_t)(s * 32)) + kxA) ^ xorv;
        const uint32_t ktB = (((uint32_t)(s * 32)) + kxB) ^ xorv;
#pragma unroll
        for (int mi = 0; mi < 4; mi++)
            ldsm4(ah[buf][mi], sb + A_O + rowA + mi * 2048 + ktA);
#pragma unroll
        for (int j = 0; j < 4; j++)
            ldsm4(bh[buf][j], sb + B_O + rowB + j * 2048 + ktB);
    };

    const int NCH = KDIM / 64;
#pragma unroll 1
    for (int c = 0; c < NCH; c++) {
        cp_wait<1>();
        __syncthreads();
        if (c + 2 < NCH) issue(c + 2, (c + 2) % 3);
        cp_commit();
        const uint32_t sb = su + (c % 3) * STAGE_B;
        load_frags(sb, 0, 0);
#pragma unroll
        for (int s = 0; s < 4; s++) {
            const int cur = s & 1;
            if (s < 3) load_frags(sb, s + 1, cur ^ 1);
#pragma unroll
            for (int mi = 0; mi < 4; mi++)
#pragma unroll
                for (int nj = 0; nj < 8; nj++)
                    mma16816(acc[mi][nj], ah[cur][mi],
                             &bh[cur][nj >> 1][(nj & 1) * 2]);
        }
    }

    // ---- epilogue ----
    const int g = lane >> 2, t4 = lane & 3;
    if (P1) {
#pragma unroll
        for (int mi = 0; mi < 4; mi++) {
            int r0 = warp_m + mi * 16 + g;
#pragma unroll
            for (int nj = 0; nj < 8; nj++) {
                int cB = warp_n + nj * 8 + 2 * t4;
                float b0v = sbias[cB], b1v = sbias[cB + 1];
                float v00 = geluf(acc[mi][nj][0] + b0v);
                float v01 = geluf(acc[mi][nj][1] + b1v);
                float v10 = geluf(acc[mi][nj][2] + b0v);
                float v11 = geluf(acc[mi][nj][3] + b1v);
                size_t gc = (size_t)nt * BN + cB;
                __half2 p0 = __floats2half2_rn(v00, v01);
                __half2 p1 = __floats2half2_rn(v10, v11);
                *(uint32_t*)(g_hh + (size_t)(row0 + r0) * DHID + gc) =
                    *(uint32_t*)&p0;
                *(uint32_t*)(g_hh + (size_t)(row0 + r0 + 8) * DHID + gc) =
                    *(uint32_t*)&p1;
            }
        }
    } else {
#pragma unroll
        for (int mi = 0; mi < 4; mi++) {
            int r0 = warp_m + mi * 16 + g;
            float* y0 = g_y + (size_t)(row0 + r0) * DOUT + (size_t)nt * BN;
            float* y1 = g_y + (size_t)(row0 + r0 + 8) * DOUT + (size_t)nt * BN;
#pragma unroll
            for (int nj = 0; nj < 8; nj++) {
                int cB = warp_n + nj * 8 + 2 * t4;
                float b0v = sbias[cB], b1v = sbias[cB + 1];
                *(float2*)(y0 + cB) =
                    make_float2(acc[mi][nj][0] + b0v, acc[mi][nj][1] + b1v);
                *(float2*)(y1 + cB) =
                    make_float2(acc[mi][nj][2] + b0v, acc[mi][nj][3] + b1v);
            }
        }
    }
}

// ---------------------------------------------------------------------------
extern "C" void kernel_launch(void* const* d_in, const int* in_sizes, int n_in,
                              void* d_out, int out_size) {
    const float* x  = (const float*)d_in[0];
    const float* gw = (const float*)d_in[1];
    const float* w1 = (const float*)d_in[2];
    const float* b1 = (const float*)d_in[3];
    const float* w2 = (const float*)d_in[4];
    const float* b2 = (const float*)d_in[5];
    float* out = (float*)d_out;

    cudaFuncSetAttribute(mma_gemm<DIN, true>,
                         cudaFuncAttributeMaxDynamicSharedMemorySize, DYN_BYTES);
    cudaFuncSetAttribute(mma_gemm<DHID, false>,
                         cudaFuncAttributeMaxDynamicSharedMemorySize, DYN_BYTES);

    gate_kernel<<<GATE_B + XCONV_B, 256>>>(x, gw);
    assign_kernel<<<NEXP, 1024>>>();

    mma_gemm<DIN, true><<<dim3(W1C_X + NMT + W2C_X, DHID / BN), 128,
                          DYN_BYTES>>>(b1, (const float4*)w1,
                                       (const float4*)w2);
    mma_gemm<DHID, false><<<dim3(DOUT / BN, NMT), 128, DYN_BYTES>>>(
        b2, nullptr, nullptr);
    combine_kernel<<<BATCH, 256>>>(out);
}

// round 16
// speedup vs baseline: 1.0289x; 1.0226x over previous
#include <cuda_runtime.h>
#include <cuda_fp16.h>
#include <math.h>
#include <stdint.h>

// ---------------------------------------------------------------------------
// MoE top-2-of-8 via pure fp16 HMMA (fp32 accumulate).
// R16: R13 baseline (best-known structure) + pass1 gelu switched from
// erff (~20 ops) to tanh.approx-based gelu (~5 ops): pass1 runs 8704 tiles
// x 16K gelu evals; erff was ~5-7% of pass1 issue. RMS error added ~1e-4,
// quadrature with 4.24e-4 existing -> ~4.4e-4 << 1e-3.
// Structure: gate(+w1/x conv) -> assign(1024thr) -> pass1(+w2 conv rows)
// -> pass2 (2-D independent grid) -> combine. GEMM mainloop = R11.
// ---------------------------------------------------------------------------

#define BATCH 8192
#define NEXP  8
#define DIN   2048
#define DHID  8192
#define DOUT  2048

#define BM 128
#define BN 128
#define MAX_ROWS 17408
#define NMT (MAX_ROWS / BM)

#define A_O 0
#define B_O 16384
#define STAGE_B 32768
#define DYN_BYTES (3 * STAGE_B + 1024)

#define GATE_B 1024
#define W1CONV_B 2048
#define XCONV_B 256
#define W2CONV_X 64

#define SWZ(o) ((o) ^ (((o) >> 3) & 0x70))

// ---- device scratch --------------------------------------------------------
__device__ __half g_w1h[(size_t)NEXP * DHID * DIN];
__device__ __half g_w2h[(size_t)NEXP * DOUT * DHID];
__device__ __half g_xh[(size_t)BATCH * DIN];
__device__ __half g_hh[(size_t)MAX_ROWS * DHID];
__device__ float  g_y[(size_t)MAX_ROWS * DOUT];

__device__ int   g_tok_e[BATCH * 2];
__device__ float g_tok_p[BATCH * 2];
__device__ int   g_tok_slot[BATCH * 2];
__device__ int   g_pair_token[MAX_ROWS];
__device__ int   g_offsets[NEXP + 1];

// ---- helpers ----------------------------------------------------------------
__device__ __forceinline__ uint32_t smem_u32(const void* p) {
    uint32_t a;
    asm("{ .reg .u64 t; cvta.to.shared.u64 t, %1; cvt.u32.u64 %0, t; }"
        : "=r"(a) : "l"(p));
    return a;
}
__device__ __forceinline__ void cp16(uint32_t s, const void* g) {
    asm volatile("cp.async.cg.shared.global [%0], [%1], 16;" :: "r"(s), "l"(g));
}
__device__ __forceinline__ void cp_commit() {
    asm volatile("cp.async.commit_group;" ::: "memory");
}
template <int N>
__device__ __forceinline__ void cp_wait() {
    asm volatile("cp.async.wait_group %0;" :: "n"(N) : "memory");
}
__device__ __forceinline__ void ldsm4(uint32_t* r, uint32_t addr) {
    asm volatile("ldmatrix.sync.aligned.m8n8.x4.shared.b16 {%0,%1,%2,%3}, [%4];"
                 : "=r"(r[0]), "=r"(r[1]), "=r"(r[2]), "=r"(r[3]) : "r"(addr));
}
__device__ __forceinline__ void mma16816(float* d, const uint32_t* a,
                                         const uint32_t* b) {
    asm volatile(
        "mma.sync.aligned.m16n8k16.row.col.f32.f16.f16.f32 "
        "{%0,%1,%2,%3}, {%4,%5,%6,%7}, {%8,%9}, {%0,%1,%2,%3};"
        : "+f"(d[0]), "+f"(d[1]), "+f"(d[2]), "+f"(d[3])
        : "r"(a[0]), "r"(a[1]), "r"(a[2]), "r"(a[3]), "r"(b[0]), "r"(b[1]));
}
// tanh-approx gelu: 0.5v(1 + tanh(0.7978845608(v + 0.044715 v^3)))
__device__ __forceinline__ float geluf(float v) {
    float u = 0.7978845608028654f * fmaf(0.044715f * v, v * v, v);
    float t;
    asm("tanh.approx.f32 %0, %1;" : "=f"(t) : "f"(u));
    return 0.5f * v * (1.0f + t);
}
__device__ __forceinline__ void conv4(const float4* __restrict__ src,
                                      uint2* __restrict__ dst, size_t i) {
    float4 v = src[i];
    __half2 h0 = __floats2half2_rn(v.x, v.y);
    __half2 h1 = __floats2half2_rn(v.z, v.w);
    dst[i] = make_uint2(*(uint32_t*)&h0, *(uint32_t*)&h1);
}

// ---------------------------------------------------------------------------
// Gating + fused w1/x fp16 conversion.
__global__ void gate_kernel(const float* __restrict__ x,
                            const float* __restrict__ gw,
                            const float4* __restrict__ w1src) {
    int b = blockIdx.x;
    if (b >= GATE_B) {
        int cb = b - GATE_B;
        if (cb < W1CONV_B) {
            size_t base = (size_t)cb * 16384;
            uint2* dst = (uint2*)g_w1h;
            for (size_t i = base + threadIdx.x; i < base + 16384; i += 256)
                conv4(w1src, dst, i);
        } else {
            size_t base = (size_t)(cb - W1CONV_B) * 16384;
            const float4* xs = (const float4*)x;
            uint2* dst = (uint2*)g_xh;
            for (size_t i = base + threadIdx.x; i < base + 16384; i += 256)
                conv4(xs, dst, i);
        }
        return;
    }
    int gtid = b * blockDim.x + threadIdx.x;
    int t = gtid >> 5;
    int lane = gtid & 31;
    if (t >= BATCH) return;
    const float* xr = x + (size_t)t * DIN;
    float acc[NEXP];
#pragma unroll
    for (int e = 0; e < NEXP; e++) acc[e] = 0.0f;
    for (int k = lane; k < DIN; k += 32) {
        float xv = __ldg(xr + k);
#pragma unroll
        for (int e = 0; e < NEXP; e++) acc[e] += xv * __ldg(gw + e * DIN + k);
    }
#pragma unroll
    for (int off = 16; off > 0; off >>= 1) {
#pragma unroll
        for (int e = 0; e < NEXP; e++)
            acc[e] += __shfl_xor_sync(0xffffffffu, acc[e], off);
    }
    if (lane == 0) {
        float v0 = -1e30f, v1 = -1e30f;
        int i0 = 0, i1 = 0;
#pragma unroll
        for (int e = 0; e < NEXP; e++) {
            float v = acc[e];
            if (v > v0) { v1 = v0; i1 = i0; v0 = v; i0 = e; }
            else if (v > v1) { v1 = v; i1 = e; }
        }
        float e1 = expf(v1 - v0);
        float s = 1.0f + e1;
        g_tok_e[2 * t + 0] = i0;
        g_tok_e[2 * t + 1] = i1;
        g_tok_p[2 * t + 0] = 1.0f / s;
        g_tok_p[2 * t + 1] = e1 / s;
    }
}

// Fused counts + offsets + ordered compaction + padding zero. 1024 threads.
__global__ void assign_kernel() {
    int e = blockIdx.x;
    __shared__ int cnt[NEXP];
    __shared__ int wcnt[32];
    if (threadIdx.x < NEXP) cnt[threadIdx.x] = 0;
    __syncthreads();
    for (int t = threadIdx.x; t < BATCH; t += 1024) {
        atomicAdd(&cnt[g_tok_e[2 * t + 0]], 1);
        atomicAdd(&cnt[g_tok_e[2 * t + 1]], 1);
    }
    __syncthreads();
    int base = 0;
    for (int i = 0; i < e; i++) base += ((cnt[i] + BM - 1) / BM) * BM;
    const int my_cnt = cnt[e];
    const int my_pad = ((my_cnt + BM - 1) / BM) * BM;
    if (e == 0 && threadIdx.x == 0) {
        int off = 0;
        for (int i = 0; i < NEXP; i++) {
            g_offsets[i] = off;
            off += ((cnt[i] + BM - 1) / BM) * BM;
        }
        g_offsets[NEXP] = off;
    }
    for (int i = base + my_cnt + threadIdx.x; i < base + my_pad; i += 1024)
        g_pair_token[i] = 0;

    int lane = threadIdx.x & 31;
    int wid = threadIdx.x >> 5;
    int run = base;
    for (int t0 = 0; t0 < BATCH; t0 += 1024) {
        int t = t0 + threadIdx.x;
        int sel = 0, kk = 0;
        int e0 = g_tok_e[2 * t], e1 = g_tok_e[2 * t + 1];
        if (e0 == e)      { sel = 1; kk = 0; }
        else if (e1 == e) { sel = 1; kk = 1; }
        unsigned m = __ballot_sync(0xffffffffu, sel);
        if (lane == 0) wcnt[wid] = __popc(m);
        __syncthreads();
        int prefix = 0, tot = 0;
#pragma unroll
        for (int i = 0; i < 32; i++) {
            if (i < wid) prefix += wcnt[i];
            tot += wcnt[i];
        }
        if (sel) {
            int pos = run + prefix + __popc(m & ((1u << lane) - 1u));
            g_pair_token[pos] = t;
            g_tok_slot[2 * t + kk] = pos;
        }
        run += tot;
        __syncthreads();
    }
}

// out[t] = p0 * y[slot0] + p1 * y[slot1]
__global__ void combine_kernel(float* __restrict__ out) {
    int t = blockIdx.x;
    int s0 = g_tok_slot[2 * t], s1 = g_tok_slot[2 * t + 1];
    float p0 = g_tok_p[2 * t], p1 = g_tok_p[2 * t + 1];
    const float4* y0 = (const float4*)(g_y + (size_t)s0 * DOUT);
    const float4* y1 = (const float4*)(g_y + (size_t)s1 * DOUT);
    float4* o = (float4*)(out + (size_t)t * DOUT);
#pragma unroll
    for (int i = threadIdx.x; i < DOUT / 4; i += 256) {
        float4 a = y0[i], b = y1[i];
        o[i] = make_float4(p0 * a.x + p1 * b.x, p0 * a.y + p1 * b.y,
                           p0 * a.z + p1 * b.z, p0 * a.w + p1 * b.w);
    }
}

// ---------------------------------------------------------------------------
// Grouped GEMM: C[128x128] = A[128xK] * B[128xK]^T, fp16 HMMA.
// 4 warps, 2x2 warp grid, 64x64 warp tile, 2 CTAs/SM, frag double-buffer,
// aligned B-register pairs.
// ---------------------------------------------------------------------------
template <int KDIM, bool P1>
__global__ void __launch_bounds__(128, 2)
mma_gemm(const float* __restrict__ bias, const float4* __restrict__ wconv) {
    const int mt = P1 ? blockIdx.x : blockIdx.y;
    const int nt = P1 ? blockIdx.y : blockIdx.x;

    if (P1 && mt >= NMT) {            // fused w2 converter
        size_t base = ((size_t)(mt - NMT) * gridDim.y + blockIdx.y) * 8192;
        uint2* dst = (uint2*)g_w2h;
        for (size_t i = base + threadIdx.x; i < base + 8192; i += 128)
            conv4(wconv, dst, i);
        return;
    }

    __shared__ int s_off[NEXP + 1];
    __shared__ int stok[BM];
    __shared__ float sbias[BN];
    extern __shared__ char dsm[];

    const int tid = threadIdx.x;
    if (tid < NEXP + 1) s_off[tid] = g_offsets[tid];
    __syncthreads();
    const int row0 = mt * BM;
    if (row0 >= s_off[NEXP]) return;
    int e = 0;
    while (row0 >= s_off[e + 1]) e++;
    if (P1) stok[tid] = g_pair_token[row0 + tid];
    sbias[tid] = bias[(size_t)e * (P1 ? DHID : DOUT) + (size_t)nt * BN + tid];
    __syncthreads();

    const __half* Ag = P1 ? g_xh : g_hh;
    const __half* Bg = P1 ? g_w1h : g_w2h;

    uintptr_t pal = ((uintptr_t)dsm + 1023) & ~(uintptr_t)1023;
    const uint32_t su = smem_u32((void*)pal);

    // ---- producer mapping ----
    const int ch = tid & 7;
    const int rb = tid >> 3;
    uint32_t aOff[8];
    const size_t brow0 = (size_t)e * (P1 ? DHID : DOUT) + (size_t)nt * BN;
    const __half* bP0 = Bg + (brow0 + rb) * (size_t)KDIM + ch * 8;
#pragma unroll
    for (int i = 0; i < 8; i++) {
        int r = rb + i * 16;
        size_t ga = P1 ? (size_t)stok[r] * KDIM : (size_t)(row0 + r) * KDIM;
        aOff[i] = (uint32_t)((ga + ch * 8) * 2);
    }
    const uint32_t swz0 = SWZ((uint32_t)rb * 128 + (uint32_t)ch * 16);
    const char* Agb = (const char*)Ag;

    auto issue = [&](int kt, int st) {
        uint32_t sb = su + st * STAGE_B;
        uint32_t ko = (uint32_t)kt * 128;
#pragma unroll
        for (int i = 0; i < 8; i++)
            cp16(sb + A_O + swz0 + i * 2048, Agb + aOff[i] + ko);
#pragma unroll
        for (int i = 0; i < 8; i++)
            cp16(sb + B_O + swz0 + i * 2048,
                 bP0 + (size_t)i * 16 * KDIM + kt * 64);
    };

    issue(0, 0);
    cp_commit();
    issue(1, 1);
    cp_commit();

    // ---- consumer mapping ----
    const int wid = tid >> 5, lane = tid & 31;
    const int warp_m = (wid >> 1) * 64;
    const int warp_n = (wid & 1) * 64;
    const uint32_t xorv = (uint32_t)(lane & 7) << 4;
    const uint32_t kxA = (uint32_t)((lane >> 4) << 4);
    const uint32_t rowA =
        (uint32_t)(warp_m + (lane & 7) + ((lane >> 3) & 1) * 8) * 128;
    const uint32_t kxB = (uint32_t)(((lane >> 3) & 1) << 4);
    const uint32_t rowB =
        (uint32_t)(warp_n + (lane & 7) + ((lane >> 4) & 1) * 8) * 128;

    float acc[4][8][4];
#pragma unroll
    for (int i = 0; i < 4; i++)
#pragma unroll
        for (int j = 0; j < 8; j++)
#pragma unroll
            for (int q = 0; q < 4; q++) acc[i][j][q] = 0.0f;

    uint32_t ah[2][4][4], bh[2][4][4];

    auto load_frags = [&](uint32_t sb, int s, int buf) {
        const uint32_t ktA = (((uint32_t)(s * 32)) + kxA) ^ xorv;
        const uint32_t ktB = (((uint32_t)(s * 32)) + kxB) ^ xorv;
#pragma unroll
        for (int mi = 0; mi < 4; mi++)
            ldsm4(ah[buf][mi], sb + A_O + rowA + mi * 2048 + ktA);
#pragma unroll
        for (int j = 0; j < 4; j++)
            ldsm4(bh[buf][j], sb + B_O + rowB + j * 2048 + ktB);
    };

    const int NCH = KDIM / 64;
#pragma unroll 1
    for (int c = 0; c < NCH; c++) {
        cp_wait<1>();
        __syncthreads();
        if (c + 2 < NCH) issue(c + 2, (c + 2) % 3);
        cp_commit();
        const uint32_t sb = su + (c % 3) * STAGE_B;
        load_frags(sb, 0, 0);
#pragma unroll
        for (int s = 0; s < 4; s++) {
            const int cur = s & 1;
            if (s < 3) load_frags(sb, s + 1, cur ^ 1);
#pragma unroll
            for (int mi = 0; mi < 4; mi++)
#pragma unroll
                for (int nj = 0; nj < 8; nj++)
                    mma16816(acc[mi][nj], ah[cur][mi],
                             &bh[cur][nj >> 1][(nj & 1) * 2]);
        }
    }

    // ---- epilogue ----
    const int g = lane >> 2, t4 = lane & 3;
    if (P1) {
#pragma unroll
        for (int mi = 0; mi < 4; mi++) {
            int r0 = warp_m + mi * 16 + g;
#pragma unroll
            for (int nj = 0; nj < 8; nj++) {
                int cB = warp_n + nj * 8 + 2 * t4;
                float b0v = sbias[cB], b1v = sbias[cB + 1];
                float v00 = geluf(acc[mi][nj][0] + b0v);
                float v01 = geluf(acc[mi][nj][1] + b1v);
                float v10 = geluf(acc[mi][nj][2] + b0v);
                float v11 = geluf(acc[mi][nj][3] + b1v);
                size_t gc = (size_t)nt * BN + cB;
                __half2 p0 = __floats2half2_rn(v00, v01);
                __half2 p1 = __floats2half2_rn(v10, v11);
                *(uint32_t*)(g_hh + (size_t)(row0 + r0) * DHID + gc) =
                    *(uint32_t*)&p0;
                *(uint32_t*)(g_hh + (size_t)(row0 + r0 + 8) * DHID + gc) =
                    *(uint32_t*)&p1;
            }
        }
    } else {
#pragma unroll
        for (int mi = 0; mi < 4; mi++) {
            int r0 = warp_m + mi * 16 + g;
            float* y0 = g_y + (size_t)(row0 + r0) * DOUT + (size_t)nt * BN;
            float* y1 = g_y + (size_t)(row0 + r0 + 8) * DOUT + (size_t)nt * BN;
#pragma unroll
            for (int nj = 0; nj < 8; nj++) {
                int cB = warp_n + nj * 8 + 2 * t4;
                float b0v = sbias[cB], b1v = sbias[cB + 1];
                *(float2*)(y0 + cB) =
                    make_float2(acc[mi][nj][0] + b0v, acc[mi][nj][1] + b1v);
                *(float2*)(y1 + cB) =
                    make_float2(acc[mi][nj][2] + b0v, acc[mi][nj][3] + b1v);
            }
        }
    }
}

// ---------------------------------------------------------------------------
extern "C" void kernel_launch(void* const* d_in, const int* in_sizes, int n_in,
                              void* d_out, int out_size) {
    const float* x  = (const float*)d_in[0];
    const float* gw = (const float*)d_in[1];
    const float* w1 = (const float*)d_in[2];
    const float* b1 = (const float*)d_in[3];
    const float* w2 = (const float*)d_in[4];
    const float* b2 = (const float*)d_in[5];
    float* out = (float*)d_out;

    cudaFuncSetAttribute(mma_gemm<DIN, true>,
                         cudaFuncAttributeMaxDynamicSharedMemorySize, DYN_BYTES);
    cudaFuncSetAttribute(mma_gemm<DHID, false>,
                         cudaFuncAttributeMaxDynamicSharedMemorySize, DYN_BYTES);

    gate_kernel<<<GATE_B + W1CONV_B + XCONV_B, 256>>>(x, gw, (const float4*)w1);
    assign_kernel<<<NEXP, 1024>>>();

    mma_gemm<DIN, true><<<dim3(NMT + W2CONV_X, DHID / BN), 128, DYN_BYTES>>>(
        b1, (const float4*)w2);
    mma_gemm<DHID, false><<<dim3(DOUT / BN, NMT), 128, DYN_BYTES>>>(b2, nullptr);
    combine_kernel<<<BATCH, 256>>>(out);
}

// round 17
// speedup vs baseline: 1.0421x; 1.0128x over previous
#include <cuda_runtime.h>
#include <cuda_fp16.h>
#include <math.h>
#include <stdint.h>

// ---------------------------------------------------------------------------
// MoE top-2-of-8 via pure fp16 HMMA (fp32 accumulate).
// R17: R16 + pass2 y-scratch stored as fp16 (half2 packs) instead of fp32:
// pass2-epilogue + combine DRAM traffic 270MB -> 170MB; y is O(1) so fp16
// rounding adds ~1e-4 RMS (quadrature: 4.70e-4 -> ~4.8e-4 < 1e-3).
// Structure: gate(+w1/x conv) -> assign(1024thr) -> pass1(tanh-gelu, +w2
// conv rows) -> pass2 (independent 2-D grid) -> combine. Mainloop = R11.
// ---------------------------------------------------------------------------

#define BATCH 8192
#define NEXP  8
#define DIN   2048
#define DHID  8192
#define DOUT  2048

#define BM 128
#define BN 128
#define MAX_ROWS 17408
#define NMT (MAX_ROWS / BM)

#define A_O 0
#define B_O 16384
#define STAGE_B 32768
#define DYN_BYTES (3 * STAGE_B + 1024)

#define GATE_B 1024
#define W1CONV_B 2048
#define XCONV_B 256
#define W2CONV_X 64

#define SWZ(o) ((o) ^ (((o) >> 3) & 0x70))

// ---- device scratch --------------------------------------------------------
__device__ __half g_w1h[(size_t)NEXP * DHID * DIN];
__device__ __half g_w2h[(size_t)NEXP * DOUT * DHID];
__device__ __half g_xh[(size_t)BATCH * DIN];
__device__ __half g_hh[(size_t)MAX_ROWS * DHID];
__device__ __half g_yh[(size_t)MAX_ROWS * DOUT];   // fp16 y-scratch (R17)

__device__ int   g_tok_e[BATCH * 2];
__device__ float g_tok_p[BATCH * 2];
__device__ int   g_tok_slot[BATCH * 2];
__device__ int   g_pair_token[MAX_ROWS];
__device__ int   g_offsets[NEXP + 1];

// ---- helpers ----------------------------------------------------------------
__device__ __forceinline__ uint32_t smem_u32(const void* p) {
    uint32_t a;
    asm("{ .reg .u64 t; cvta.to.shared.u64 t, %1; cvt.u32.u64 %0, t; }"
        : "=r"(a) : "l"(p));
    return a;
}
__device__ __forceinline__ void cp16(uint32_t s, const void* g) {
    asm volatile("cp.async.cg.shared.global [%0], [%1], 16;" :: "r"(s), "l"(g));
}
__device__ __forceinline__ void cp_commit() {
    asm volatile("cp.async.commit_group;" ::: "memory");
}
template <int N>
__device__ __forceinline__ void cp_wait() {
    asm volatile("cp.async.wait_group %0;" :: "n"(N) : "memory");
}
__device__ __forceinline__ void ldsm4(uint32_t* r, uint32_t addr) {
    asm volatile("ldmatrix.sync.aligned.m8n8.x4.shared.b16 {%0,%1,%2,%3}, [%4];"
                 : "=r"(r[0]), "=r"(r[1]), "=r"(r[2]), "=r"(r[3]) : "r"(addr));
}
__device__ __forceinline__ void mma16816(float* d, const uint32_t* a,
                                         const uint32_t* b) {
    asm volatile(
        "mma.sync.aligned.m16n8k16.row.col.f32.f16.f16.f32 "
        "{%0,%1,%2,%3}, {%4,%5,%6,%7}, {%8,%9}, {%0,%1,%2,%3};"
        : "+f"(d[0]), "+f"(d[1]), "+f"(d[2]), "+f"(d[3])
        : "r"(a[0]), "r"(a[1]), "r"(a[2]), "r"(a[3]), "r"(b[0]), "r"(b[1]));
}
// tanh-approx gelu: 0.5v(1 + tanh(0.7978845608(v + 0.044715 v^3)))
__device__ __forceinline__ float geluf(float v) {
    float u = 0.7978845608028654f * fmaf(0.044715f * v, v * v, v);
    float t;
    asm("tanh.approx.f32 %0, %1;" : "=f"(t) : "f"(u));
    return 0.5f * v * (1.0f + t);
}
__device__ __forceinline__ void conv4(const float4* __restrict__ src,
                                      uint2* __restrict__ dst, size_t i) {
    float4 v = src[i];
    __half2 h0 = __floats2half2_rn(v.x, v.y);
    __half2 h1 = __floats2half2_rn(v.z, v.w);
    dst[i] = make_uint2(*(uint32_t*)&h0, *(uint32_t*)&h1);
}

// ---------------------------------------------------------------------------
// Gating + fused w1/x fp16 conversion.
__global__ void gate_kernel(const float* __restrict__ x,
                            const float* __restrict__ gw,
                            const float4* __restrict__ w1src) {
    int b = blockIdx.x;
    if (b >= GATE_B) {
        int cb = b - GATE_B;
        if (cb < W1CONV_B) {
            size_t base = (size_t)cb * 16384;
            uint2* dst = (uint2*)g_w1h;
            for (size_t i = base + threadIdx.x; i < base + 16384; i += 256)
                conv4(w1src, dst, i);
        } else {
            size_t base = (size_t)(cb - W1CONV_B) * 16384;
            const float4* xs = (const float4*)x;
            uint2* dst = (uint2*)g_xh;
            for (size_t i = base + threadIdx.x; i < base + 16384; i += 256)
                conv4(xs, dst, i);
        }
        return;
    }
    int gtid = b * blockDim.x + threadIdx.x;
    int t = gtid >> 5;
    int lane = gtid & 31;
    if (t >= BATCH) return;
    const float* xr = x + (size_t)t * DIN;
    float acc[NEXP];
#pragma unroll
    for (int e = 0; e < NEXP; e++) acc[e] = 0.0f;
    for (int k = lane; k < DIN; k += 32) {
        float xv = __ldg(xr + k);
#pragma unroll
        for (int e = 0; e < NEXP; e++) acc[e] += xv * __ldg(gw + e * DIN + k);
    }
#pragma unroll
    for (int off = 16; off > 0; off >>= 1) {
#pragma unroll
        for (int e = 0; e < NEXP; e++)
            acc[e] += __shfl_xor_sync(0xffffffffu, acc[e], off);
    }
    if (lane == 0) {
        float v0 = -1e30f, v1 = -1e30f;
        int i0 = 0, i1 = 0;
#pragma unroll
        for (int e = 0; e < NEXP; e++) {
            float v = acc[e];
            if (v > v0) { v1 = v0; i1 = i0; v0 = v; i0 = e; }
            else if (v > v1) { v1 = v; i1 = e; }
        }
        float e1 = expf(v1 - v0);
        float s = 1.0f + e1;
        g_tok_e[2 * t + 0] = i0;
        g_tok_e[2 * t + 1] = i1;
        g_tok_p[2 * t + 0] = 1.0f / s;
        g_tok_p[2 * t + 1] = e1 / s;
    }
}

// Fused counts + offsets + ordered compaction + padding zero. 1024 threads.
__global__ void assign_kernel() {
    int e = blockIdx.x;
    __shared__ int cnt[NEXP];
    __shared__ int wcnt[32];
    if (threadIdx.x < NEXP) cnt[threadIdx.x] = 0;
    __syncthreads();
    for (int t = threadIdx.x; t < BATCH; t += 1024) {
        atomicAdd(&cnt[g_tok_e[2 * t + 0]], 1);
        atomicAdd(&cnt[g_tok_e[2 * t + 1]], 1);
    }
    __syncthreads();
    int base = 0;
    for (int i = 0; i < e; i++) base += ((cnt[i] + BM - 1) / BM) * BM;
    const int my_cnt = cnt[e];
    const int my_pad = ((my_cnt + BM - 1) / BM) * BM;
    if (e == 0 && threadIdx.x == 0) {
        int off = 0;
        for (int i = 0; i < NEXP; i++) {
            g_offsets[i] = off;
            off += ((cnt[i] + BM - 1) / BM) * BM;
        }
        g_offsets[NEXP] = off;
    }
    for (int i = base + my_cnt + threadIdx.x; i < base + my_pad; i += 1024)
        g_pair_token[i] = 0;

    int lane = threadIdx.x & 31;
    int wid = threadIdx.x >> 5;
    int run = base;
    for (int t0 = 0; t0 < BATCH; t0 += 1024) {
        int t = t0 + threadIdx.x;
        int sel = 0, kk = 0;
        int e0 = g_tok_e[2 * t], e1 = g_tok_e[2 * t + 1];
        if (e0 == e)      { sel = 1; kk = 0; }
        else if (e1 == e) { sel = 1; kk = 1; }
        unsigned m = __ballot_sync(0xffffffffu, sel);
        if (lane == 0) wcnt[wid] = __popc(m);
        __syncthreads();
        int prefix = 0, tot = 0;
#pragma unroll
        for (int i = 0; i < 32; i++) {
            if (i < wid) prefix += wcnt[i];
            tot += wcnt[i];
        }
        if (sel) {
            int pos = run + prefix + __popc(m & ((1u << lane) - 1u));
            g_pair_token[pos] = t;
            g_tok_slot[2 * t + kk] = pos;
        }
        run += tot;
        __syncthreads();
    }
}

// out[t] = p0 * y[slot0] + p1 * y[slot1]   (y read as fp16)
__global__ void combine_kernel(float* __restrict__ out) {
    int t = blockIdx.x;
    int s0 = g_tok_slot[2 * t], s1 = g_tok_slot[2 * t + 1];
    float p0 = g_tok_p[2 * t], p1 = g_tok_p[2 * t + 1];
    const uint2* y0 = (const uint2*)(g_yh + (size_t)s0 * DOUT);
    const uint2* y1 = (const uint2*)(g_yh + (size_t)s1 * DOUT);
    float4* o = (float4*)(out + (size_t)t * DOUT);
#pragma unroll
    for (int i = threadIdx.x; i < DOUT / 4; i += 256) {
        uint2 ua = y0[i], ub = y1[i];
        float2 a0 = __half22float2(*(__half2*)&ua.x);
        float2 a1 = __half22float2(*(__half2*)&ua.y);
        float2 b0 = __half22float2(*(__half2*)&ub.x);
        float2 b1 = __half22float2(*(__half2*)&ub.y);
        o[i] = make_float4(p0 * a0.x + p1 * b0.x, p0 * a0.y + p1 * b0.y,
                           p0 * a1.x + p1 * b1.x, p0 * a1.y + p1 * b1.y);
    }
}

// ---------------------------------------------------------------------------
// Grouped GEMM: C[128x128] = A[128xK] * B[128xK]^T, fp16 HMMA.
// 4 warps, 2x2 warp grid, 64x64 warp tile, 2 CTAs/SM, frag double-buffer,
// aligned B-register pairs.
// ---------------------------------------------------------------------------
template <int KDIM, bool P1>
__global__ void __launch_bounds__(128, 2)
mma_gemm(const float* __restrict__ bias, const float4* __restrict__ wconv) {
    const int mt = P1 ? blockIdx.x : blockIdx.y;
    const int nt = P1 ? blockIdx.y : blockIdx.x;

    if (P1 && mt >= NMT) {            // fused w2 converter
        size_t base = ((size_t)(mt - NMT) * gridDim.y + blockIdx.y) * 8192;
        uint2* dst = (uint2*)g_w2h;
        for (size_t i = base + threadIdx.x; i < base + 8192; i += 128)
            conv4(wconv, dst, i);
        return;
    }

    __shared__ int s_off[NEXP + 1];
    __shared__ int stok[BM];
    __shared__ float sbias[BN];
    extern __shared__ char dsm[];

    const int tid = threadIdx.x;
    if (tid < NEXP + 1) s_off[tid] = g_offsets[tid];
    __syncthreads();
    const int row0 = mt * BM;
    if (row0 >= s_off[NEXP]) return;
    int e = 0;
    while (row0 >= s_off[e + 1]) e++;
    if (P1) stok[tid] = g_pair_token[row0 + tid];
    sbias[tid] = bias[(size_t)e * (P1 ? DHID : DOUT) + (size_t)nt * BN + tid];
    __syncthreads();

    const __half* Ag = P1 ? g_xh : g_hh;
    const __half* Bg = P1 ? g_w1h : g_w2h;

    uintptr_t pal = ((uintptr_t)dsm + 1023) & ~(uintptr_t)1023;
    const uint32_t su = smem_u32((void*)pal);

    // ---- producer mapping ----
    const int ch = tid & 7;
    const int rb = tid >> 3;
    uint32_t aOff[8];
    const size_t brow0 = (size_t)e * (P1 ? DHID : DOUT) + (size_t)nt * BN;
    const __half* bP0 = Bg + (brow0 + rb) * (size_t)KDIM + ch * 8;
#pragma unroll
    for (int i = 0; i < 8; i++) {
        int r = rb + i * 16;
        size_t ga = P1 ? (size_t)stok[r] * KDIM : (size_t)(row0 + r) * KDIM;
        aOff[i] = (uint32_t)((ga + ch * 8) * 2);
    }
    const uint32_t swz0 = SWZ((uint32_t)rb * 128 + (uint32_t)ch * 16);
    const char* Agb = (const char*)Ag;

    auto issue = [&](int kt, int st) {
        uint32_t sb = su + st * STAGE_B;
        uint32_t ko = (uint32_t)kt * 128;
#pragma unroll
        for (int i = 0; i < 8; i++)
            cp16(sb + A_O + swz0 + i * 2048, Agb + aOff[i] + ko);
#pragma unroll
        for (int i = 0; i < 8; i++)
            cp16(sb + B_O + swz0 + i * 2048,
                 bP0 + (size_t)i * 16 * KDIM + kt * 64);
    };

    issue(0, 0);
    cp_commit();
    issue(1, 1);
    cp_commit();

    // ---- consumer mapping ----
    const int wid = tid >> 5, lane = tid & 31;
    const int warp_m = (wid >> 1) * 64;
    const int warp_n = (wid & 1) * 64;
    const uint32_t xorv = (uint32_t)(lane & 7) << 4;
    const uint32_t kxA = (uint32_t)((lane >> 4) << 4);
    const uint32_t rowA =
        (uint32_t)(warp_m + (lane & 7) + ((lane >> 3) & 1) * 8) * 128;
    const uint32_t kxB = (uint32_t)(((lane >> 3) & 1) << 4);
    const uint32_t rowB =
        (uint32_t)(warp_n + (lane & 7) + ((lane >> 4) & 1) * 8) * 128;

    float acc[4][8][4];
#pragma unroll
    for (int i = 0; i < 4; i++)
#pragma unroll
        for (int j = 0; j < 8; j++)
#pragma unroll
            for (int q = 0; q < 4; q++) acc[i][j][q] = 0.0f;

    uint32_t ah[2][4][4], bh[2][4][4];

    auto load_frags = [&](uint32_t sb, int s, int buf) {
        const uint32_t ktA = (((uint32_t)(s * 32)) + kxA) ^ xorv;
        const uint32_t ktB = (((uint32_t)(s * 32)) + kxB) ^ xorv;
#pragma unroll
        for (int mi = 0; mi < 4; mi++)
            ldsm4(ah[buf][mi], sb + A_O + rowA + mi * 2048 + ktA);
#pragma unroll
        for (int j = 0; j < 4; j++)
            ldsm4(bh[buf][j], sb + B_O + rowB + j * 2048 + ktB);
    };

    const int NCH = KDIM / 64;
#pragma unroll 1
    for (int c = 0; c < NCH; c++) {
        cp_wait<1>();
        __syncthreads();
        if (c + 2 < NCH) issue(c + 2, (c + 2) % 3);
        cp_commit();
        const uint32_t sb = su + (c % 3) * STAGE_B;
        load_frags(sb, 0, 0);
#pragma unroll
        for (int s = 0; s < 4; s++) {
            const int cur = s & 1;
            if (s < 3) load_frags(sb, s + 1, cur ^ 1);
#pragma unroll
            for (int mi = 0; mi < 4; mi++)
#pragma unroll
                for (int nj = 0; nj < 8; nj++)
                    mma16816(acc[mi][nj], ah[cur][mi],
                             &bh[cur][nj >> 1][(nj & 1) * 2]);
        }
    }

    // ---- epilogue ----
    const int g = lane >> 2, t4 = lane & 3;
    if (P1) {
#pragma unroll
        for (int mi = 0; mi < 4; mi++) {
            int r0 = warp_m + mi * 16 + g;
#pragma unroll
            for (int nj = 0; nj < 8; nj++) {
                int cB = warp_n + nj * 8 + 2 * t4;
                float b0v = sbias[cB], b1v = sbias[cB + 1];
                float v00 = geluf(acc[mi][nj][0] + b0v);
                float v01 = geluf(acc[mi][nj][1] + b1v);
                float v10 = geluf(acc[mi][nj][2] + b0v);
                float v11 = geluf(acc[mi][nj][3] + b1v);
                size_t gc = (size_t)nt * BN + cB;
                __half2 p0 = __floats2half2_rn(v00, v01);
                __half2 p1 = __floats2half2_rn(v10, v11);
                *(uint32_t*)(g_hh + (size_t)(row0 + r0) * DHID + gc) =
                    *(uint32_t*)&p0;
                *(uint32_t*)(g_hh + (size_t)(row0 + r0 + 8) * DHID + gc) =
                    *(uint32_t*)&p1;
            }
        }
    } else {
#pragma unroll
        for (int mi = 0; mi < 4; mi++) {
            int r0 = warp_m + mi * 16 + g;
            __half* y0 = g_yh + (size_t)(row0 + r0) * DOUT + (size_t)nt * BN;
            __half* y1 = g_yh + (size_t)(row0 + r0 + 8) * DOUT + (size_t)nt * BN;
#pragma unroll
            for (int nj = 0; nj < 8; nj++) {
                int cB = warp_n + nj * 8 + 2 * t4;
                float b0v = sbias[cB], b1v = sbias[cB + 1];
                __half2 p0 =
                    __floats2half2_rn(acc[mi][nj][0] + b0v, acc[mi][nj][1] + b1v);
                __half2 p1 =
                    __floats2half2_rn(acc[mi][nj][2] + b0v, acc[mi][nj][3] + b1v);
                *(uint32_t*)(y0 + cB) = *(uint32_t*)&p0;
                *(uint32_t*)(y1 + cB) = *(uint32_t*)&p1;
            }
        }
    }
}

// ---------------------------------------------------------------------------
extern "C" void kernel_launch(void* const* d_in, const int* in_sizes, int n_in,
                              void* d_out, int out_size) {
    const float* x  = (const float*)d_in[0];
    const float* gw = (const float*)d_in[1];
    const float* w1 = (const float*)d_in[2];
    const float* b1 = (const float*)d_in[3];
    const float* w2 = (const float*)d_in[4];
    const float* b2 = (const float*)d_in[5];
    float* out = (float*)d_out;

    cudaFuncSetAttribute(mma_gemm<DIN, true>,
                         cudaFuncAttributeMaxDynamicSharedMemorySize, DYN_BYTES);
    cudaFuncSetAttribute(mma_gemm<DHID, false>,
                         cudaFuncAttributeMaxDynamicSharedMemorySize, DYN_BYTES);

    gate_kernel<<<GATE_B + W1CONV_B + XCONV_B, 256>>>(x, gw, (const float4*)w1);
    assign_kernel<<<NEXP, 1024>>>();

    mma_gemm<DIN, true><<<dim3(NMT + W2CONV_X, DHID / BN), 128, DYN_BYTES>>>(
        b1, (const float4*)w2);
    mma_gemm<DHID, false><<<dim3(DOUT / BN, NMT), 128, DYN_BYTES>>>(b2, nullptr);
    combine_kernel<<<BATCH, 256>>>(out);
}